// round 6
// baseline (speedup 1.0000x reference)
#include <cuda_runtime.h>
#include <math.h>
#include <stdint.h>

#define BB 4
#define CC 64
#define NP 8192
#define OO 128
#define KNN 20

// ---------------- device scratch ----------------
__device__ float g_xt[(size_t)BB * NP * CC];        // x transposed: [b][n][c]
__device__ float g_xxn[BB * NP];                    // -0.5*||x||^2
__device__ float g_uvq[(size_t)BB * NP * 256];      // [b][n][ U(64) | V(64) | Q(128) ]
__device__ int   g_idx[(size_t)BB * NP * KNN];      // top-20 neighbor indices

__device__ __forceinline__ void ffma2(unsigned long long& d,
                                      unsigned long long a,
                                      unsigned long long b) {
    asm("fma.rn.f32x2 %0, %1, %2, %0;" : "+l"(d) : "l"(a), "l"(b));
}
__device__ __forceinline__ void fadd2(unsigned long long& d,
                                      unsigned long long b) {
    asm("add.rn.f32x2 %0, %0, %1;" : "+l"(d) : "l"(b));
}
__device__ __forceinline__ unsigned long long packdup(float v) {
    unsigned long long r;
    asm("mov.b64 %0, {%1, %1};" : "=l"(r) : "f"(v));
    return r;
}

// ---------------- K0: transpose x (B,C,N) -> xt (B,N,C) ----------------
__global__ void k_transpose(const float* __restrict__ x) {
    __shared__ float tile[32][33];
    int b  = blockIdx.z;
    int c0 = blockIdx.y * 32;
    int n0 = blockIdx.x * 32;
    int tx = threadIdx.x, ty = threadIdx.y;   // 32 x 8
#pragma unroll
    for (int yy = 0; yy < 32; yy += 8)
        tile[ty + yy][tx] = x[((size_t)b * CC + c0 + ty + yy) * NP + n0 + tx];
    __syncthreads();
#pragma unroll
    for (int yy = 0; yy < 32; yy += 8)
        g_xt[((size_t)b * NP + n0 + ty + yy) * CC + c0 + tx] = tile[tx][ty + yy];
}

// ---------------- K0b: negated half squared norms ----------------
__global__ void k_norm() {
    int p = blockIdx.x * blockDim.x + threadIdx.x;
    const float4* v = (const float4*)&g_xt[(size_t)p * CC];
    float s = 0.f;
#pragma unroll
    for (int i = 0; i < 16; i++) {
        float4 q = v[i];
        s += q.x * q.x + q.y * q.y + q.z * q.z + q.w * q.w;
    }
    g_xxn[p] = -0.5f * s;
}

// ---------------- K1: precompute U, V, Q per point ----------------
__global__ __launch_bounds__(256) void k_uvq(const float* __restrict__ W1,
                                             const float* __restrict__ W2) {
    __shared__ float xts[16][64];
    int p0 = blockIdx.x * 16;
    int o  = threadIdx.x;
    for (int s = threadIdx.x; s < 16 * 64; s += 256)
        xts[s >> 6][s & 63] = g_xt[(size_t)p0 * 64 + s];

    float4 wr[16];
    if (o < 64) {
        const float* r = W1 + o * 128;
#pragma unroll
        for (int i = 0; i < 16; i++)
            wr[i] = make_float4(r[4*i], r[4*i+1], r[4*i+2], r[4*i+3]);
    } else if (o < 128) {
        const float* r = W1 + (o - 64) * 128;
#pragma unroll
        for (int i = 0; i < 16; i++)
            wr[i] = make_float4(r[64+4*i]-r[4*i], r[65+4*i]-r[4*i+1],
                                r[66+4*i]-r[4*i+2], r[67+4*i]-r[4*i+3]);
    } else {
        const float* r = W2 + (o - 128) * 128;
#pragma unroll
        for (int i = 0; i < 16; i++)
            wr[i] = make_float4(r[64+4*i]-r[4*i], r[65+4*i]-r[4*i+1],
                                r[66+4*i]-r[4*i+2], r[67+4*i]-r[4*i+3]);
    }
    __syncthreads();

    float acc[16];
#pragma unroll
    for (int p = 0; p < 16; p++) acc[p] = 0.f;
#pragma unroll
    for (int c4 = 0; c4 < 16; c4++) {
        float4 w = wr[c4];
#pragma unroll
        for (int p = 0; p < 16; p++) {
            float4 xv = *(const float4*)&xts[p][c4 * 4];
            acc[p] += w.x * xv.x + w.y * xv.y + w.z * xv.z + w.w * xv.w;
        }
    }
#pragma unroll
    for (int p = 0; p < 16; p++)
        g_uvq[((size_t)p0 + p) * 256 + o] = acc[p];
}

// ---------------- K2: kNN top-20, register-direct selection ----------------
// Rank value v(i,j) = dot(xi,xj) - 0.5*xx_j  (monotone in -dist^2)
// Thread = (row, colgroup): 1 i-row x 16 j-cols. Top-20 per thread in .local,
// inserted straight from accumulators. 4-way merge per row at the end.
#define TI 64
#define TJ 64
#define XI_OFF 0                       // [i][c] stride 68, 64 rows
#define XJ_OFF (64 * 68)               // [c][j] stride 68, 64 c-rows
#define XXN_OFF (2 * 64 * 68)          // 64
#define SMF 10304                      // >= merge area 256*20*2
#define KNN_SMEM_BYTES (SMF * 4)

#define INS(val, jj)                                              \
    do {                                                          \
        float _v = (val);                                         \
        if (_v > minv) {                                          \
            bv[minp] = _v; bi[minp] = (jj);                       \
            minv = bv[0]; minp = 0;                               \
            for (int _t = 1; _t < KNN; _t++)                      \
                if (bv[_t] < minv) { minv = bv[_t]; minp = _t; }  \
        }                                                         \
    } while (0)

__global__ void __launch_bounds__(256, 4) k_knn(const float* __restrict__ x) {
    extern __shared__ float sm[];
    float* xi  = sm + XI_OFF;
    float* xj  = sm + XJ_OFF;
    float* xxn = sm + XXN_OFF;

    int b   = blockIdx.y;
    int i0  = blockIdx.x * TI;
    int tid = threadIdx.x;
    int row = tid >> 2;                 // 0..63
    int g   = tid & 3;                  // 0..3 -> cols 16g..16g+15
    size_t base = (size_t)b * NP;
    const float* xb = x + (size_t)b * CC * NP;   // c-major [c][n]

    // xi: row-major [i][c] from g_xt (once)
    {
        int i = tid >> 2, q = tid & 3;
#pragma unroll
        for (int it = 0; it < 4; it++) {
            int c = 4 * q + 16 * it;
            float4 v = *(const float4*)&g_xt[(base + i0 + i) * 64 + c];
            *(float4*)&xi[i * 68 + c] = v;
        }
    }

    float bv[KNN]; int bi[KNN];
    float minv = -3.4e38f; int minp = 0;
    for (int t = 0; t < KNN; t++) { bv[t] = -3.4e38f; bi[t] = 0; }

    int lc0 = tid >> 4, lm = tid & 15;  // xj loader coords

    for (int jt = 0; jt < NP; jt += TJ) {
        __syncthreads();                // prior tile fully consumed
        // xj: c-major [c][j] straight from input x (coalesced, conflict-free)
#pragma unroll
        for (int it = 0; it < 4; it++) {
            int c = lc0 + 16 * it;
            float4 v = *(const float4*)&xb[(size_t)c * NP + jt + 4 * lm];
            *(float4*)&xj[c * 68 + 4 * lm] = v;
        }
        if (tid < 16) {
            float4 nv = *(const float4*)&g_xxn[base + jt + 4 * tid];
            *(float4*)&xxn[4 * tid] = nv;
        }
        __syncthreads();

        unsigned long long acc[8];
#pragma unroll
        for (int m = 0; m < 8; m++) acc[m] = 0ULL;

        const float* pb = xj + 16 * g;
        const float* pa = xi + row * 68;

#pragma unroll 4
        for (int c4 = 0; c4 < 16; c4++) {
            float4 a4 = *(const float4*)(pa + 4 * c4);
            unsigned long long p0 = packdup(a4.x);
            unsigned long long p1 = packdup(a4.y);
            unsigned long long p2 = packdup(a4.z);
            unsigned long long p3 = packdup(a4.w);
            const float* b0 = pb + (4 * c4) * 68;
            {
                ulonglong2 B0 = *(const ulonglong2*)(b0);
                ulonglong2 B1 = *(const ulonglong2*)(b0 + 4);
                ulonglong2 B2 = *(const ulonglong2*)(b0 + 8);
                ulonglong2 B3 = *(const ulonglong2*)(b0 + 12);
                ffma2(acc[0], p0, B0.x); ffma2(acc[1], p0, B0.y);
                ffma2(acc[2], p0, B1.x); ffma2(acc[3], p0, B1.y);
                ffma2(acc[4], p0, B2.x); ffma2(acc[5], p0, B2.y);
                ffma2(acc[6], p0, B3.x); ffma2(acc[7], p0, B3.y);
            }
            {
                const float* b1 = b0 + 68;
                ulonglong2 B0 = *(const ulonglong2*)(b1);
                ulonglong2 B1 = *(const ulonglong2*)(b1 + 4);
                ulonglong2 B2 = *(const ulonglong2*)(b1 + 8);
                ulonglong2 B3 = *(const ulonglong2*)(b1 + 12);
                ffma2(acc[0], p1, B0.x); ffma2(acc[1], p1, B0.y);
                ffma2(acc[2], p1, B1.x); ffma2(acc[3], p1, B1.y);
                ffma2(acc[4], p1, B2.x); ffma2(acc[5], p1, B2.y);
                ffma2(acc[6], p1, B3.x); ffma2(acc[7], p1, B3.y);
            }
            {
                const float* b2 = b0 + 136;
                ulonglong2 B0 = *(const ulonglong2*)(b2);
                ulonglong2 B1 = *(const ulonglong2*)(b2 + 4);
                ulonglong2 B2 = *(const ulonglong2*)(b2 + 8);
                ulonglong2 B3 = *(const ulonglong2*)(b2 + 12);
                ffma2(acc[0], p2, B0.x); ffma2(acc[1], p2, B0.y);
                ffma2(acc[2], p2, B1.x); ffma2(acc[3], p2, B1.y);
                ffma2(acc[4], p2, B2.x); ffma2(acc[5], p2, B2.y);
                ffma2(acc[6], p2, B3.x); ffma2(acc[7], p2, B3.y);
            }
            {
                const float* b3 = b0 + 204;
                ulonglong2 B0 = *(const ulonglong2*)(b3);
                ulonglong2 B1 = *(const ulonglong2*)(b3 + 4);
                ulonglong2 B2 = *(const ulonglong2*)(b3 + 8);
                ulonglong2 B3 = *(const ulonglong2*)(b3 + 12);
                ffma2(acc[0], p3, B0.x); ffma2(acc[1], p3, B0.y);
                ffma2(acc[2], p3, B1.x); ffma2(acc[3], p3, B1.y);
                ffma2(acc[4], p3, B2.x); ffma2(acc[5], p3, B2.y);
                ffma2(acc[6], p3, B3.x); ffma2(acc[7], p3, B3.y);
            }
        }

        // rank = dot - 0.5*xx_j, insert straight from registers
        {
            ulonglong2 n0 = *(const ulonglong2*)&xxn[16 * g];
            ulonglong2 n1 = *(const ulonglong2*)&xxn[16 * g + 4];
            ulonglong2 n2 = *(const ulonglong2*)&xxn[16 * g + 8];
            ulonglong2 n3 = *(const ulonglong2*)&xxn[16 * g + 12];
            fadd2(acc[0], n0.x); fadd2(acc[1], n0.y);
            fadd2(acc[2], n1.x); fadd2(acc[3], n1.y);
            fadd2(acc[4], n2.x); fadd2(acc[5], n2.y);
            fadd2(acc[6], n3.x); fadd2(acc[7], n3.y);
            int jb = jt + 16 * g;
#pragma unroll
            for (int m = 0; m < 8; m++) {
                float lo = __uint_as_float((unsigned)acc[m]);
                float hi = __uint_as_float((unsigned)(acc[m] >> 32));
                INS(lo, jb + 2 * m);
                INS(hi, jb + 2 * m + 1);
            }
        }
    }

    // merge: 4 partial lists per row -> exact top-20
    __syncthreads();
    float* cv = sm;                       // 256*20
    int*   ci = (int*)(sm + 5120);        // 256*20
    for (int t = 0; t < KNN; t++) {
        cv[tid * KNN + t] = bv[t];
        ci[tid * KNN + t] = bi[t];
    }
    __syncthreads();
    if (tid < TI) {
        float fv[KNN]; int fi[KNN];
        float mv = -3.4e38f; int mp = 0;
        for (int t = 0; t < KNN; t++) { fv[t] = -3.4e38f; fi[t] = 0; }
        for (int u = 0; u < 4; u++) {
            int src = (tid * 4 + u) * KNN;
            for (int t = 0; t < KNN; t++) {
                float v = cv[src + t];
                if (v > mv) {
                    fv[mp] = v; fi[mp] = ci[src + t];
                    mv = fv[0]; mp = 0;
                    for (int w = 1; w < KNN; w++)
                        if (fv[w] < mv) { mv = fv[w]; mp = w; }
                }
            }
        }
        for (int t = 0; t < KNN; t++)
            g_idx[(base + i0 + tid) * KNN + t] = fi[t];
    }
}

// ---------------- K3: fused gather + softmax gate + output GEMM ----------------
__global__ __launch_bounds__(256) void k_fuse(const float* __restrict__ W2,
                                              float* __restrict__ out) {
    __shared__ float w2as[64 * 128];
    __shared__ float t_s[16][64];
    __shared__ int   idxs[16][KNN];

    int blk = blockIdx.x;
    int b   = blk >> 9;
    int n0  = (blk & 511) * 16;
    int tid = threadIdx.x;
    size_t base = (size_t)b * NP;

    for (int s = tid; s < 8192; s += 256) {
        int o = s >> 6, c = s & 63;
        w2as[c * 128 + o] = W2[o * 128 + c];
    }
    for (int s = tid; s < 16 * KNN; s += 256)
        idxs[s / KNN][s % KNN] = g_idx[(base + n0) * KNN + s];
    __syncthreads();

    for (int pass = 0; pass < 4; pass++) {
        int pt = pass * 4 + (tid >> 6);
        int d  = tid & 63;
        float vv = g_uvq[(base + n0 + pt) * 256 + 64 + d];
        float h[KNN];
#pragma unroll
        for (int k = 0; k < KNN; k++) {
            int j = idxs[pt][k];
            h[k] = g_uvq[(base + j) * 256 + d] + vv;
        }
        float m = h[0];
#pragma unroll
        for (int k = 1; k < KNN; k++) m = fmaxf(m, h[k]);
        float S = 0.f, ws = 0.f;
#pragma unroll
        for (int k = 0; k < KNN; k++) {
            float e = __expf(h[k] - m);
            S += e;
            int j = idxs[pt][k];
            ws += g_xt[(base + j) * 64 + d] * e;
        }
        t_s[pt][d] = ws / S;
    }
    __syncthreads();

    int o = tid & 127, g = tid >> 7;
    float acc[8];
#pragma unroll
    for (int p = 0; p < 8; p++)
        acc[p] = g_uvq[(base + n0 + g * 8 + p) * 256 + 128 + o];
#pragma unroll 8
    for (int c = 0; c < 64; c++) {
        float w = w2as[c * 128 + o];
#pragma unroll
        for (int p = 0; p < 8; p++) acc[p] += w * t_s[g * 8 + p][c];
    }
    float* op = out + ((size_t)b * OO + o) * NP + n0 + g * 8;
    *(float4*)op       = make_float4(acc[0], acc[1], acc[2], acc[3]);
    *(float4*)(op + 4) = make_float4(acc[4], acc[5], acc[6], acc[7]);
}

// ---------------- launch ----------------
extern "C" void kernel_launch(void* const* d_in, const int* in_sizes, int n_in,
                              void* d_out, int out_size) {
    const float* x  = (const float*)d_in[0];
    const float* W1 = (const float*)d_in[1];
    const float* W2 = (const float*)d_in[2];
    float* out = (float*)d_out;

    cudaFuncSetAttribute(k_knn, cudaFuncAttributeMaxDynamicSharedMemorySize,
                         KNN_SMEM_BYTES);

    k_transpose<<<dim3(NP / 32, CC / 32, BB), dim3(32, 8)>>>(x);
    k_norm<<<(BB * NP) / 256, 256>>>();
    k_uvq<<<(BB * NP) / 16, 256>>>(W1, W2);
    k_knn<<<dim3(NP / TI, BB), 256, KNN_SMEM_BYTES>>>(x);
    k_fuse<<<(BB * NP) / 16, 256>>>(W2, out);
}

// round 7
// speedup vs baseline: 2.7199x; 2.7199x over previous
#include <cuda_runtime.h>
#include <math.h>
#include <stdint.h>

#define BB 4
#define CC 64
#define NP 8192
#define OO 128
#define KNN 20

// ---------------- device scratch ----------------
__device__ float g_xt[(size_t)BB * NP * CC];        // x transposed: [b][n][c]
__device__ float g_xxn[BB * NP];                    // -0.5*||x||^2
__device__ float g_uvq[(size_t)BB * NP * 256];      // [b][n][ U(64) | V(64) | Q(128) ]
__device__ int   g_idx[(size_t)BB * NP * KNN];      // top-20 neighbor indices

__device__ __forceinline__ void ffma2(unsigned long long& d,
                                      unsigned long long a,
                                      unsigned long long b) {
    asm("fma.rn.f32x2 %0, %1, %2, %0;" : "+l"(d) : "l"(a), "l"(b));
}
__device__ __forceinline__ void fadd2(unsigned long long& d,
                                      unsigned long long b) {
    asm("add.rn.f32x2 %0, %0, %1;" : "+l"(d) : "l"(b));
}
__device__ __forceinline__ unsigned long long packdup(float v) {
    unsigned long long r;
    asm("mov.b64 %0, {%1, %1};" : "=l"(r) : "f"(v));
    return r;
}

// ---------------- K0: transpose x (B,C,N) -> xt (B,N,C) ----------------
__global__ void k_transpose(const float* __restrict__ x) {
    __shared__ float tile[32][33];
    int b  = blockIdx.z;
    int c0 = blockIdx.y * 32;
    int n0 = blockIdx.x * 32;
    int tx = threadIdx.x, ty = threadIdx.y;   // 32 x 8
#pragma unroll
    for (int yy = 0; yy < 32; yy += 8)
        tile[ty + yy][tx] = x[((size_t)b * CC + c0 + ty + yy) * NP + n0 + tx];
    __syncthreads();
#pragma unroll
    for (int yy = 0; yy < 32; yy += 8)
        g_xt[((size_t)b * NP + n0 + ty + yy) * CC + c0 + tx] = tile[tx][ty + yy];
}

// ---------------- K0b: negated half squared norms ----------------
__global__ void k_norm() {
    int p = blockIdx.x * blockDim.x + threadIdx.x;
    const float4* v = (const float4*)&g_xt[(size_t)p * CC];
    float s = 0.f;
#pragma unroll
    for (int i = 0; i < 16; i++) {
        float4 q = v[i];
        s += q.x * q.x + q.y * q.y + q.z * q.z + q.w * q.w;
    }
    g_xxn[p] = -0.5f * s;
}

// ---------------- K1: precompute U, V, Q per point ----------------
__global__ __launch_bounds__(256) void k_uvq(const float* __restrict__ W1,
                                             const float* __restrict__ W2) {
    __shared__ float xts[16][64];
    int p0 = blockIdx.x * 16;
    int o  = threadIdx.x;
    for (int s = threadIdx.x; s < 16 * 64; s += 256)
        xts[s >> 6][s & 63] = g_xt[(size_t)p0 * 64 + s];

    float4 wr[16];
    if (o < 64) {
        const float* r = W1 + o * 128;
#pragma unroll
        for (int i = 0; i < 16; i++)
            wr[i] = make_float4(r[4*i], r[4*i+1], r[4*i+2], r[4*i+3]);
    } else if (o < 128) {
        const float* r = W1 + (o - 64) * 128;
#pragma unroll
        for (int i = 0; i < 16; i++)
            wr[i] = make_float4(r[64+4*i]-r[4*i], r[65+4*i]-r[4*i+1],
                                r[66+4*i]-r[4*i+2], r[67+4*i]-r[4*i+3]);
    } else {
        const float* r = W2 + (o - 128) * 128;
#pragma unroll
        for (int i = 0; i < 16; i++)
            wr[i] = make_float4(r[64+4*i]-r[4*i], r[65+4*i]-r[4*i+1],
                                r[66+4*i]-r[4*i+2], r[67+4*i]-r[4*i+3]);
    }
    __syncthreads();

    float acc[16];
#pragma unroll
    for (int p = 0; p < 16; p++) acc[p] = 0.f;
#pragma unroll
    for (int c4 = 0; c4 < 16; c4++) {
        float4 w = wr[c4];
#pragma unroll
        for (int p = 0; p < 16; p++) {
            float4 xv = *(const float4*)&xts[p][c4 * 4];
            acc[p] += w.x * xv.x + w.y * xv.y + w.z * xv.z + w.w * xv.w;
        }
    }
#pragma unroll
    for (int p = 0; p < 16; p++)
        g_uvq[((size_t)p0 + p) * 256 + o] = acc[p];
}

// ---------------- K2: kNN top-20, 128x128 tile, 8x8 packed micro-tile ----------------
// Rank value v(i,j) = dot(xi,xj) - 0.5*xx_j  (monotone in -dist^2)
#define TI 128
#define TJ 128
#define XI_OFF 0                        // [c][i] stride 132 -> 8448
#define XJ_OFF 8448                     // [c][j] stride 132 -> 8448
#define DS_OFF 16896                    // 128 x 68 -> 8704
#define XXN_OFF 25600                   // 128
#define SMF 25728
#define KNN_SMEM_BYTES (SMF * 4)

#define INS(val, jj)                                              \
    do {                                                          \
        float _v = (val);                                         \
        if (_v > minv) {                                          \
            bv[minp] = _v; bi[minp] = (jj);                       \
            minv = bv[0]; minp = 0;                               \
            for (int _t = 1; _t < KNN; _t++)                      \
                if (bv[_t] < minv) { minv = bv[_t]; minp = _t; }  \
        }                                                         \
    } while (0)

__global__ void __launch_bounds__(256, 2) k_knn(const float* __restrict__ x) {
    extern __shared__ float sm[];
    float* xi  = sm + XI_OFF;
    float* xj  = sm + XJ_OFF;
    float* Ds  = sm + DS_OFF;
    float* xxn = sm + XXN_OFF;

    int b   = blockIdx.y;
    int i0  = blockIdx.x * TI;
    int tid = threadIdx.x;
    int ty  = tid >> 4;                 // 0..15 -> rows 8ty..8ty+7
    int tx  = tid & 15;                 // 0..15 -> cols 8tx..8tx+7
    size_t base = (size_t)b * NP;
    const float* xb = x + (size_t)b * CC * NP;   // c-major [c][n]

    // xi: [c][i] from input x (coalesced), once
#pragma unroll
    for (int m = 0; m < 8; m++) {
        int s  = tid + 256 * m;         // 0..2047
        int c  = s >> 5;                // 0..63
        int i4 = (s & 31) << 2;         // 0..124
        *(float4*)&xi[c * 132 + i4] = *(const float4*)&xb[(size_t)c * NP + i0 + i4];
    }

    float bv[KNN]; int bi[KNN];
    float minv = -3.4e38f; int minp = 0;
    for (int t = 0; t < KNN; t++) { bv[t] = -3.4e38f; bi[t] = 0; }

    const float* pa = xi + 8 * ty;
    const float* pb = xj + 8 * tx;
    int hsel = tx >> 3;                 // which 64-col half this thread writes
    int lc   = 8 * (tx & 7);            // local col base within half

    for (int jt = 0; jt < NP; jt += TJ) {
        __syncthreads();                // prior tile fully consumed
#pragma unroll
        for (int m = 0; m < 8; m++) {
            int s  = tid + 256 * m;
            int c  = s >> 5;
            int j4 = (s & 31) << 2;
            *(float4*)&xj[c * 132 + j4] = *(const float4*)&xb[(size_t)c * NP + jt + j4];
        }
        if (tid < 32)
            *(float4*)&xxn[4 * tid] = *(const float4*)&g_xxn[base + jt + 4 * tid];
        __syncthreads();

        unsigned long long acc[8][4];
#pragma unroll
        for (int i = 0; i < 8; i++)
#pragma unroll
            for (int p = 0; p < 4; p++) acc[i][p] = 0ULL;

#pragma unroll 4
        for (int c = 0; c < 64; c++) {
            float4 a0 = *(const float4*)(pa + c * 132);
            float4 a1 = *(const float4*)(pa + c * 132 + 4);
            ulonglong2 b0 = *(const ulonglong2*)(pb + c * 132);
            ulonglong2 b1 = *(const ulonglong2*)(pb + c * 132 + 4);
            unsigned long long A[8];
            A[0] = packdup(a0.x); A[1] = packdup(a0.y);
            A[2] = packdup(a0.z); A[3] = packdup(a0.w);
            A[4] = packdup(a1.x); A[5] = packdup(a1.y);
            A[6] = packdup(a1.z); A[7] = packdup(a1.w);
#pragma unroll
            for (int i = 0; i < 8; i++) {
                ffma2(acc[i][0], A[i], b0.x);
                ffma2(acc[i][1], A[i], b0.y);
                ffma2(acc[i][2], A[i], b1.x);
                ffma2(acc[i][3], A[i], b1.y);
            }
        }

        // two 64-col rounds: write Ds (rank = dot - 0.5 xx_j), scan with all threads
#pragma unroll
        for (int h = 0; h < 2; h++) {
            if (hsel == h) {
                ulonglong2 n0 = *(const ulonglong2*)&xxn[8 * tx];
                ulonglong2 n1 = *(const ulonglong2*)&xxn[8 * tx + 4];
#pragma unroll
                for (int i = 0; i < 8; i++) {
                    unsigned long long s0 = acc[i][0], s1 = acc[i][1];
                    unsigned long long s2 = acc[i][2], s3 = acc[i][3];
                    fadd2(s0, n0.x); fadd2(s1, n0.y);
                    fadd2(s2, n1.x); fadd2(s3, n1.y);
                    union { unsigned long long u[2]; float4 f; } U0, U1;
                    U0.u[0] = s0; U0.u[1] = s1;
                    U1.u[0] = s2; U1.u[1] = s3;
                    int row = 8 * ty + i;
                    *(float4*)&Ds[row * 68 + lc]     = U0.f;
                    *(float4*)&Ds[row * 68 + lc + 4] = U1.f;
                }
            }
            __syncthreads();
            {
                int row = tid >> 1, sub = tid & 1;
                int jb = jt + 64 * h + 32 * sub;
                const float* p = &Ds[row * 68 + 32 * sub];
#pragma unroll
                for (int m = 0; m < 8; m++) {
                    float4 v = *(const float4*)(p + 4 * m);
                    INS(v.x, jb + 4 * m + 0);
                    INS(v.y, jb + 4 * m + 1);
                    INS(v.z, jb + 4 * m + 2);
                    INS(v.w, jb + 4 * m + 3);
                }
            }
            __syncthreads();
        }
    }

    // merge: 2 partial lists per row -> exact top-20
    __syncthreads();
    float* cv = sm;                       // 256*20
    int*   ci = (int*)(sm + 5120);        // 256*20
    for (int t = 0; t < KNN; t++) {
        cv[tid * KNN + t] = bv[t];
        ci[tid * KNN + t] = bi[t];
    }
    __syncthreads();
    if (tid < TI) {
        float fv[KNN]; int fi[KNN];
        float mv = -3.4e38f; int mp = 0;
        for (int t = 0; t < KNN; t++) { fv[t] = -3.4e38f; fi[t] = 0; }
        for (int u = 0; u < 2; u++) {
            int src = (tid * 2 + u) * KNN;
            for (int t = 0; t < KNN; t++) {
                float v = cv[src + t];
                if (v > mv) {
                    fv[mp] = v; fi[mp] = ci[src + t];
                    mv = fv[0]; mp = 0;
                    for (int w = 1; w < KNN; w++)
                        if (fv[w] < mv) { mv = fv[w]; mp = w; }
                }
            }
        }
        for (int t = 0; t < KNN; t++)
            g_idx[(base + i0 + tid) * KNN + t] = fi[t];
    }
}

// ---------------- K3: fused gather + softmax gate + output GEMM ----------------
__global__ __launch_bounds__(256) void k_fuse(const float* __restrict__ W2,
                                              float* __restrict__ out) {
    __shared__ float w2as[64 * 128];
    __shared__ float t_s[16][64];
    __shared__ int   idxs[16][KNN];

    int blk = blockIdx.x;
    int b   = blk >> 9;
    int n0  = (blk & 511) * 16;
    int tid = threadIdx.x;
    size_t base = (size_t)b * NP;

    for (int s = tid; s < 8192; s += 256) {
        int o = s >> 6, c = s & 63;
        w2as[c * 128 + o] = W2[o * 128 + c];
    }
    for (int s = tid; s < 16 * KNN; s += 256)
        idxs[s / KNN][s % KNN] = g_idx[(base + n0) * KNN + s];
    __syncthreads();

    for (int pass = 0; pass < 4; pass++) {
        int pt = pass * 4 + (tid >> 6);
        int d  = tid & 63;
        float vv = g_uvq[(base + n0 + pt) * 256 + 64 + d];
        float h[KNN];
#pragma unroll
        for (int k = 0; k < KNN; k++) {
            int j = idxs[pt][k];
            h[k] = g_uvq[(base + j) * 256 + d] + vv;
        }
        float m = h[0];
#pragma unroll
        for (int k = 1; k < KNN; k++) m = fmaxf(m, h[k]);
        float S = 0.f, ws = 0.f;
#pragma unroll
        for (int k = 0; k < KNN; k++) {
            float e = __expf(h[k] - m);
            S += e;
            int j = idxs[pt][k];
            ws += g_xt[(base + j) * 64 + d] * e;
        }
        t_s[pt][d] = ws / S;
    }
    __syncthreads();

    int o = tid & 127, g = tid >> 7;
    float acc[8];
#pragma unroll
    for (int p = 0; p < 8; p++)
        acc[p] = g_uvq[(base + n0 + g * 8 + p) * 256 + 128 + o];
#pragma unroll 8
    for (int c = 0; c < 64; c++) {
        float w = w2as[c * 128 + o];
#pragma unroll
        for (int p = 0; p < 8; p++) acc[p] += w * t_s[g * 8 + p][c];
    }
    float* op = out + ((size_t)b * OO + o) * NP + n0 + g * 8;
    *(float4*)op       = make_float4(acc[0], acc[1], acc[2], acc[3]);
    *(float4*)(op + 4) = make_float4(acc[4], acc[5], acc[6], acc[7]);
}

// ---------------- launch ----------------
extern "C" void kernel_launch(void* const* d_in, const int* in_sizes, int n_in,
                              void* d_out, int out_size) {
    const float* x  = (const float*)d_in[0];
    const float* W1 = (const float*)d_in[1];
    const float* W2 = (const float*)d_in[2];
    float* out = (float*)d_out;

    cudaFuncSetAttribute(k_knn, cudaFuncAttributeMaxDynamicSharedMemorySize,
                         KNN_SMEM_BYTES);

    k_transpose<<<dim3(NP / 32, CC / 32, BB), dim3(32, 8)>>>(x);
    k_norm<<<(BB * NP) / 256, 256>>>();
    k_uvq<<<(BB * NP) / 16, 256>>>(W1, W2);
    k_knn<<<dim3(NP / TI, BB), 256, KNN_SMEM_BYTES>>>(x);
    k_fuse<<<(BB * NP) / 16, 256>>>(W2, out);
}